// round 8
// baseline (speedup 1.0000x reference)
#include <cuda_runtime.h>
#include <cfloat>

// ChamferDistance: x,y = [16, 4096, 3] fp32 -> scalar
// R8: exact NN via 1D sorted-axis two-pointer scan. db bin-sorted by y into
//     2048 fine bins (shared); per query: expand left/right pointers from the
//     query's bin, terminate each side when the monotone bin-edge bound (with
//     one-bin slack for fp safety) proves no improvement. Exact + bitwise
//     deterministic (min equals distance to the unique true NN, computed by an
//     identical fma chain regardless of intra-bin scatter order).

#define NB      16
#define NPTS    4096
#define SPLITS  4
#define QPB     (NPTS / SPLITS)   // 1024 queries per block
#define THREADS 256
#define PPT     (QPB / THREADS)   // 4 queries per thread
#define NBLOCKS (NB * 2 * SPLITS) // 128
#define NBIN    2048
#define BPT     (NBIN / THREADS)  // 8 bins per thread in the scan

__device__ float g_partial[NBLOCKS];
__device__ unsigned int g_ticket;   // zero-init; reset by last block each run

struct SmemLayout {
    float4 pts[NPTS];          // bin-sorted db points (x,y,z,|p|^2)   64 KB
    float  blo[NPTS];          // bin lower edge per sorted position   16 KB
    int    cnt[NBIN];          //                                       8 KB
    int    off[NBIN];          // bin start offsets                     8 KB
    int    cur[NBIN];          //                                       8 KB
    int    part[THREADS];
    float  mm[2][THREADS / 32];
    float  redf[THREADS / 32];
    float  ymin, ymax;
    bool   amlast;
};

__global__ __launch_bounds__(THREADS, 1) void chamfer_kernel(
    const float* __restrict__ x, const float* __restrict__ y,
    float* __restrict__ out)
{
    extern __shared__ char sraw[];
    SmemLayout* s = (SmemLayout*)sraw;

    const int tid = threadIdx.x;
    const int wid = tid >> 5, lid = tid & 31;
    const int dir = blockIdx.y;       // 0: query=x, db=y ; 1: query=y, db=x
    const int b   = blockIdx.z;
    const float* __restrict__ q  = (dir ? y : x) + (size_t)b * NPTS * 3;
    const float* __restrict__ db = (dir ? x : y) + (size_t)b * NPTS * 3;

    // ---- Pass A: y min/max of db ----
    float lmin = FLT_MAX, lmax = -FLT_MAX;
    for (int j = tid; j < NPTS; j += THREADS) {
        float py = db[3 * j + 1];
        lmin = fminf(lmin, py); lmax = fmaxf(lmax, py);
    }
#pragma unroll
    for (int o = 16; o > 0; o >>= 1) {
        lmin = fminf(lmin, __shfl_xor_sync(0xFFFFFFFFu, lmin, o));
        lmax = fmaxf(lmax, __shfl_xor_sync(0xFFFFFFFFu, lmax, o));
    }
    if (lid == 0) { s->mm[0][wid] = lmin; s->mm[1][wid] = lmax; }
    for (int c = tid; c < NBIN; c += THREADS) s->cnt[c] = 0;
    __syncthreads();
    if (tid == 0) {
        float a0 = FLT_MAX, a1 = -FLT_MAX;
#pragma unroll
        for (int w = 0; w < THREADS / 32; w++) {
            a0 = fminf(a0, s->mm[0][w]); a1 = fmaxf(a1, s->mm[1][w]);
        }
        s->ymin = a0; s->ymax = a1;
    }
    __syncthreads();

    const float ymin = s->ymin;
    const float W    = fmaxf((s->ymax - ymin) / NBIN, 1e-30f);
    const float inv  = 1.0f / W;

    // ---- Pass B: histogram by y-bin ----
    for (int j = tid; j < NPTS; j += THREADS) {
        float py = db[3 * j + 1];
        int c = min(max((int)((py - ymin) * inv), 0), NBIN - 1);
        atomicAdd(&s->cnt[c], 1);
    }
    __syncthreads();

    // ---- Exclusive prefix sum over 2048 bins ----
    {
        const int base = tid * BPT;
        int sum = 0;
#pragma unroll
        for (int u = 0; u < BPT; u++) sum += s->cnt[base + u];
        s->part[tid] = sum;
        __syncthreads();
        for (int o = 1; o < THREADS; o <<= 1) {
            int v = (tid >= o) ? s->part[tid - o] : 0;
            __syncthreads();
            s->part[tid] += v;
            __syncthreads();
        }
        int run = (tid > 0) ? s->part[tid - 1] : 0;
#pragma unroll
        for (int u = 0; u < BPT; u++) {
            s->off[base + u] = run;
            s->cur[base + u] = run;
            run += s->cnt[base + u];
        }
    }
    __syncthreads();

    // ---- Pass C: scatter (bin-sorted; intra-bin order irrelevant) ----
    for (int j = tid; j < NPTS; j += THREADS) {
        float px = db[3 * j + 0], py = db[3 * j + 1], pz = db[3 * j + 2];
        int c = min(max((int)((py - ymin) * inv), 0), NBIN - 1);
        int pos = atomicAdd(&s->cur[c], 1);
        s->pts[pos] = make_float4(px, py, pz, fmaf(px, px, fmaf(py, py, pz * pz)));
        s->blo[pos] = ymin + (float)c * W;   // monotone over positions
    }
    __syncthreads();

    // ---- Queries: two-pointer scan outward from own bin ----
    float ssum = 0.0f;
    const int qbase = blockIdx.x * QPB + tid * PPT;
#pragma unroll 1
    for (int p = 0; p < PPT; p++) {
        const int i = qbase + p;
        const float qx = q[3 * i + 0], qy = q[3 * i + 1], qz = q[3 * i + 2];
        const float q2 = fmaf(qx, qx, fmaf(qy, qy, qz * qz));
        const float n0 = -2.0f * qx, n1 = -2.0f * qy, n2 = -2.0f * qz;

        const int bq = min(max((int)((qy - ymin) * inv), 0), NBIN - 1);
        int pr = s->off[bq];    // first point with bin >= bq
        int pl = pr - 1;
        float bestt = FLT_MAX;  // dist = bestt + q2
        bool doneR = false, doneL = false;

        while (true) {
            if (!doneR) {
                if (pr >= NPTS) doneR = true;
                else {
                    // points at >= pr have y >= blo[pr] - W (one-bin fp slack)
                    float gap = s->blo[pr] - W - qy;
                    if (gap > 0.0f && gap * gap >= bestt + q2) doneR = true;
                    else {
                        float4 v = s->pts[pr];
                        float t = fmaf(n0, v.x, fmaf(n1, v.y, fmaf(n2, v.z, v.w)));
                        bestt = fminf(bestt, t);
                        pr++;
                    }
                }
            }
            if (!doneL) {
                if (pl < 0) doneL = true;
                else {
                    // points at <= pl have y <= blo[pl] + 2W (edge + fp slack)
                    float gap = qy - (s->blo[pl] + 2.0f * W);
                    if (gap > 0.0f && gap * gap >= bestt + q2) doneL = true;
                    else {
                        float4 v = s->pts[pl];
                        float t = fmaf(n0, v.x, fmaf(n1, v.y, fmaf(n2, v.z, v.w)));
                        bestt = fminf(bestt, t);
                        pl--;
                    }
                }
            }
            if (doneR && doneL) break;
        }
        ssum += bestt + q2;
    }

    // ---- Block reduction (fixed order -> deterministic) ----
#pragma unroll
    for (int o = 16; o > 0; o >>= 1) ssum += __shfl_down_sync(0xFFFFFFFFu, ssum, o);
    if (lid == 0) s->redf[wid] = ssum;
    __syncthreads();
    if (tid == 0) {
        float t = 0.0f;
#pragma unroll
        for (int w = 0; w < THREADS / 32; w++) t += s->redf[w];
        const int lin = blockIdx.x + SPLITS * (blockIdx.y + 2 * blockIdx.z);
        g_partial[lin] = t;
        __threadfence();
        unsigned int old = atomicAdd(&g_ticket, 1u);
        s->amlast = (old == NBLOCKS - 1);
    }
    __syncthreads();

    if (s->amlast) {
        float v = (tid < NBLOCKS) ? g_partial[tid] : 0.0f;
#pragma unroll
        for (int o = 16; o > 0; o >>= 1) v += __shfl_down_sync(0xFFFFFFFFu, v, o);
        if (lid == 0) s->redf[wid] = v;
        __syncthreads();
        if (tid == 0) {
            float t = 0.0f;
#pragma unroll
            for (int w = 0; w < THREADS / 32; w++) t += s->redf[w];
            out[0] = t * (1.0f / ((float)NB * (float)NPTS));
            g_ticket = 0;   // reset for next graph replay
        }
    }
}

extern "C" void kernel_launch(void* const* d_in, const int* in_sizes, int n_in,
                              void* d_out, int out_size)
{
    const float* x = (const float*)d_in[0];
    const float* y = (const float*)d_in[1];
    float* out = (float*)d_out;

    const int smem = (int)sizeof(SmemLayout);   // ~106 KB
    cudaFuncSetAttribute(chamfer_kernel,
                         cudaFuncAttributeMaxDynamicSharedMemorySize, smem);

    dim3 grid(SPLITS, 2, NB);
    chamfer_kernel<<<grid, THREADS, smem>>>(x, y, out);
}

// round 9
// speedup vs baseline: 4.0535x; 4.0535x over previous
#include <cuda_runtime.h>
#include <cfloat>

// ChamferDistance: x,y = [16, 4096, 3] fp32 -> scalar
// R9: warp-lockstep pruned NN. db AND queries bin-sorted by radius r=|p|;
//     each warp takes 32 consecutive sorted queries (lanes ~equal r) and runs
//     ONE shared two-pointer over the r-sorted db: warp-uniform pointers,
//     broadcast LDS of each candidate, per-lane running min, per-side
//     termination by __all_sync vote on the annulus bound
//     (|r_p - r_q| with monotone bin-edge bounds + 1-bin fp slack).
//     Exact (conservative bounds); deterministic query->lane assignment via
//     intra-bin index-sort fix; db intra-bin order cannot change the min.

#define NB      16
#define NPTS    4096
#define SPLITS  4
#define QPB     (NPTS / SPLITS)   // 1024 queries per block
#define THREADS 256
#define NWARP   (THREADS / 32)    // 8
#define QPW     (QPB / NWARP)     // 128 queries per warp
#define GRP     (QPW / 32)        // 4 groups of 32 per warp
#define NBLOCKS (NB * 2 * SPLITS) // 128
#define NBIN    1024
#define BPT     (NBIN / THREADS)  // 4 bins per thread in scans
#define CH      4                 // points per side per vote

__device__ float g_partial[NBLOCKS];
__device__ unsigned int g_ticket;   // zero-init; reset by last block each run

struct SmemLayout {
    float4 pts[NPTS];          // r-sorted db (x,y,z,|p|^2)        64 KB
    float  rlo[NPTS];          // bin lower edge per position      16 KB
    float4 qpts[QPB];          // r-sorted queries (x,y,z,|q|^2)   16 KB
    int    qidx[QPB];          // original index (for stable fix)   4 KB
    int    dboff[NBIN + 1];    //                                   4 KB
    int    qoff[NBIN + 1];     //                                   4 KB
    int    cnt[NBIN];          // scratch histogram                 4 KB
    int    cur[NBIN];          // scratch scatter cursor            4 KB
    int    part[THREADS];      // block scan workspace              1 KB
    float  wmax[NWARP];
    float  redf[NWARP];
    float  rmax;
    bool   amlast;
};

__global__ __launch_bounds__(THREADS, 1) void chamfer_kernel(
    const float* __restrict__ x, const float* __restrict__ y,
    float* __restrict__ out)
{
    extern __shared__ char sraw[];
    SmemLayout* s = (SmemLayout*)sraw;

    const int tid = threadIdx.x;
    const int wid = tid >> 5, lid = tid & 31;
    const unsigned FULL = 0xFFFFFFFFu;
    const int dir = blockIdx.y;       // 0: query=x, db=y ; 1: query=y, db=x
    const int b   = blockIdx.z;
    const float* __restrict__ q  = (dir ? y : x) + (size_t)b * NPTS * 3 + (size_t)blockIdx.x * QPB * 3;
    const float* __restrict__ db = (dir ? x : y) + (size_t)b * NPTS * 3;

    // ---- Pass A: max |p|^2 over db ----
    float lmax = 0.0f;
    for (int j = tid; j < NPTS; j += THREADS) {
        float a = db[3 * j], c = db[3 * j + 1], d = db[3 * j + 2];
        lmax = fmaxf(lmax, fmaf(a, a, fmaf(c, c, d * d)));
    }
#pragma unroll
    for (int o = 16; o > 0; o >>= 1)
        lmax = fmaxf(lmax, __shfl_xor_sync(FULL, lmax, o));
    if (lid == 0) s->wmax[wid] = lmax;
    for (int c = tid; c < NBIN; c += THREADS) s->cnt[c] = 0;
    __syncthreads();
    if (tid == 0) {
        float a = 0.0f;
#pragma unroll
        for (int w = 0; w < NWARP; w++) a = fmaxf(a, s->wmax[w]);
        s->rmax = sqrtf(a) + 1e-12f;
    }
    __syncthreads();

    const float W   = fmaxf(s->rmax * (1.0f / NBIN), 1e-30f);
    const float inv = 1.0f / W;

    // ---- Pass B: db histogram by r-bin ----
    for (int j = tid; j < NPTS; j += THREADS) {
        float a = db[3 * j], c = db[3 * j + 1], d = db[3 * j + 2];
        float r = sqrtf(fmaf(a, a, fmaf(c, c, d * d)));
        int cbin = min((int)(r * inv), NBIN - 1);
        atomicAdd(&s->cnt[cbin], 1);
    }
    __syncthreads();

    // ---- Scan -> dboff, cur ----
    {
        const int base = tid * BPT;
        int sum = 0;
#pragma unroll
        for (int u = 0; u < BPT; u++) sum += s->cnt[base + u];
        s->part[tid] = sum;
        __syncthreads();
        for (int o = 1; o < THREADS; o <<= 1) {
            int v = (tid >= o) ? s->part[tid - o] : 0;
            __syncthreads();
            s->part[tid] += v;
            __syncthreads();
        }
        int run = (tid > 0) ? s->part[tid - 1] : 0;
#pragma unroll
        for (int u = 0; u < BPT; u++) {
            s->dboff[base + u] = run;
            s->cur[base + u]   = run;
            run += s->cnt[base + u];
        }
        if (tid == THREADS - 1) s->dboff[NBIN] = NPTS;
    }
    __syncthreads();

    // ---- Pass C: scatter db (intra-bin order cannot affect the result) ----
    for (int j = tid; j < NPTS; j += THREADS) {
        float a = db[3 * j], c = db[3 * j + 1], d = db[3 * j + 2];
        float p2 = fmaf(a, a, fmaf(c, c, d * d));
        float r  = sqrtf(p2);
        int cbin = min((int)(r * inv), NBIN - 1);
        int pos = atomicAdd(&s->cur[cbin], 1);
        s->pts[pos] = make_float4(a, c, d, p2);
        s->rlo[pos] = (float)cbin * W;     // monotone over positions
    }
    __syncthreads();

    // ---- Pass D: query histogram + scan + scatter + stable fix ----
    for (int c = tid; c < NBIN; c += THREADS) s->cnt[c] = 0;
    __syncthreads();
    for (int j = tid; j < QPB; j += THREADS) {
        float a = q[3 * j], c = q[3 * j + 1], d = q[3 * j + 2];
        float r = sqrtf(fmaf(a, a, fmaf(c, c, d * d)));
        int cbin = min((int)(r * inv), NBIN - 1);
        atomicAdd(&s->cnt[cbin], 1);
    }
    __syncthreads();
    {
        const int base = tid * BPT;
        int sum = 0;
#pragma unroll
        for (int u = 0; u < BPT; u++) sum += s->cnt[base + u];
        s->part[tid] = sum;
        __syncthreads();
        for (int o = 1; o < THREADS; o <<= 1) {
            int v = (tid >= o) ? s->part[tid - o] : 0;
            __syncthreads();
            s->part[tid] += v;
            __syncthreads();
        }
        int run = (tid > 0) ? s->part[tid - 1] : 0;
#pragma unroll
        for (int u = 0; u < BPT; u++) {
            s->qoff[base + u] = run;
            s->cur[base + u]  = run;
            run += s->cnt[base + u];
        }
        if (tid == THREADS - 1) s->qoff[NBIN] = QPB;
    }
    __syncthreads();
    for (int j = tid; j < QPB; j += THREADS) {
        float a = q[3 * j], c = q[3 * j + 1], d = q[3 * j + 2];
        float q2 = fmaf(a, a, fmaf(c, c, d * d));
        float r  = sqrtf(q2);
        int cbin = min((int)(r * inv), NBIN - 1);
        int pos = atomicAdd(&s->cur[cbin], 1);
        s->qpts[pos] = make_float4(a, c, d, q2);
        s->qidx[pos] = j;
    }
    __syncthreads();
    // stable fix: within each bin, order by original index -> deterministic
    for (int c = tid; c < NBIN; c += THREADS) {
        int lo = s->qoff[c], hi = s->qoff[c + 1];
        for (int i = lo + 1; i < hi; i++) {
            float4 pv = s->qpts[i]; int iv = s->qidx[i];
            int j2 = i - 1;
            while (j2 >= lo && s->qidx[j2] > iv) {
                s->qpts[j2 + 1] = s->qpts[j2];
                s->qidx[j2 + 1] = s->qidx[j2];
                j2--;
            }
            s->qpts[j2 + 1] = pv; s->qidx[j2 + 1] = iv;
        }
    }
    __syncthreads();

    // ---- Main: per group of 32 sorted queries, shared lockstep two-pointer ----
    float ssum = 0.0f;
#pragma unroll 1
    for (int g = 0; g < GRP; g++) {
        const float4 Q = s->qpts[wid * QPW + g * 32 + lid];
        const float q2 = Q.w;
        const float rq = sqrtf(q2);
        const float n0 = -2.0f * Q.x, n1 = -2.0f * Q.y, n2 = -2.0f * Q.z;

        int cb = min((int)(rq * inv), NBIN - 1);
        int c15 = __shfl_sync(FULL, cb, 15);       // group-center bin (uniform)
        int pr = s->dboff[c15];                     // warp-uniform pointers
        int pl = pr - 1;
        float bestt = FLT_MAX;                      // dist^2 = bestt + q2
        bool doneR = (pr >= NPTS), doneL = (pl < 0);

        while (!(doneR && doneL)) {
            if (!doneR) {                           // warp-uniform branch
                const int e = min(pr + CH, NPTS);
#pragma unroll
                for (int k = 0; k < CH; k++) {
                    int pos = pr + k;
                    if (pos < e) {
                        float4 v = s->pts[pos];     // broadcast LDS.128
                        float t = fmaf(n0, v.x, fmaf(n1, v.y, fmaf(n2, v.z, v.w)));
                        bestt = fminf(bestt, t);
                    }
                }
                pr = e;
                if (pr >= NPTS) doneR = true;
                else {
                    float gap = (s->rlo[pr] - W) - rq;   // r of remaining >= rlo-W
                    bool md = (gap > 0.0f) && (gap * gap >= bestt + q2);
                    doneR = __all_sync(FULL, md);
                }
            }
            if (!doneL) {
                const int e = max(pl - CH, -1);
#pragma unroll
                for (int k = 0; k < CH; k++) {
                    int pos = pl - k;
                    if (pos > e) {
                        float4 v = s->pts[pos];
                        float t = fmaf(n0, v.x, fmaf(n1, v.y, fmaf(n2, v.z, v.w)));
                        bestt = fminf(bestt, t);
                    }
                }
                pl = e;
                if (pl < 0) doneL = true;
                else {
                    float gap = rq - (s->rlo[pl] + 2.0f * W);  // r of remaining <= rlo+2W
                    bool md = (gap > 0.0f) && (gap * gap >= bestt + q2);
                    doneL = __all_sync(FULL, md);
                }
            }
        }
        ssum += bestt + q2;
    }

    // ---- Block reduction (fixed order -> deterministic) ----
#pragma unroll
    for (int o = 16; o > 0; o >>= 1) ssum += __shfl_down_sync(FULL, ssum, o);
    if (lid == 0) s->redf[wid] = ssum;
    __syncthreads();
    if (tid == 0) {
        float t = 0.0f;
#pragma unroll
        for (int w = 0; w < NWARP; w++) t += s->redf[w];
        const int lin = blockIdx.x + SPLITS * (blockIdx.y + 2 * blockIdx.z);
        g_partial[lin] = t;
        __threadfence();
        unsigned int old = atomicAdd(&g_ticket, 1u);
        s->amlast = (old == NBLOCKS - 1);
    }
    __syncthreads();

    if (s->amlast) {
        float v = (tid < NBLOCKS) ? g_partial[tid] : 0.0f;
#pragma unroll
        for (int o = 16; o > 0; o >>= 1) v += __shfl_down_sync(FULL, v, o);
        if (lid == 0) s->redf[wid] = v;
        __syncthreads();
        if (tid == 0) {
            float t = 0.0f;
#pragma unroll
            for (int w = 0; w < NWARP; w++) t += s->redf[w];
            out[0] = t * (1.0f / ((float)NB * (float)NPTS));
            g_ticket = 0;   // reset for next graph replay
        }
    }
}

extern "C" void kernel_launch(void* const* d_in, const int* in_sizes, int n_in,
                              void* d_out, int out_size)
{
    const float* x = (const float*)d_in[0];
    const float* y = (const float*)d_in[1];
    float* out = (float*)d_out;

    const int smem = (int)sizeof(SmemLayout);   // ~118 KB
    cudaFuncSetAttribute(chamfer_kernel,
                         cudaFuncAttributeMaxDynamicSharedMemorySize, smem);

    dim3 grid(SPLITS, 2, NB);
    chamfer_kernel<<<grid, THREADS, smem>>>(x, y, out);
}

// round 10
// speedup vs baseline: 6.7139x; 1.6563x over previous
#include <cuda_runtime.h>
#include <cfloat>

// ChamferDistance: x,y = [16, 4096, 3] fp32 -> scalar
// R10: precomputed-window lockstep NN. db bin-sorted by y into SoA (shared);
//      queries bin-sorted by y (stable). Each warp: 64 consecutive sorted
//      queries (2/lane). Phase A: fixed 128-pt central slab scan -> per-query
//      NN upper bound d_ub. Window = bin range covering [y-d_ub, y+d_ub]
//      (+2-bin fp slack), computed ONCE via warp reduces. Phase B: vote-free
//      brute-force loop (packed FFMA2, broadcast LDS.128) over the window.
//      Exact (d_ub >= d_NN always) and deterministic (window always contains
//      the true NN; min value computed by identical fma chain; sum order
//      fixed by stable query sort).

#define NB      16
#define NPTS    4096
#define SPLITS  4
#define QPB     (NPTS / SPLITS)   // 1024 queries per block
#define THREADS 256
#define NWARP   (THREADS / 32)    // 8
#define GSIZE   64                // queries per warp-group (2 per lane)
#define NGRP    (QPB / GSIZE)     // 16
#define GPW     (NGRP / NWARP)    // 2 groups per warp
#define NBLOCKS (NB * 2 * SPLITS) // 128
#define NBIN    1024
#define BPT     (NBIN / THREADS)  // 4
#define CENT    128               // central slab size (phase A)

__device__ float g_partial[NBLOCKS];
__device__ unsigned int g_ticket;   // zero-init; reset by last block each run

typedef unsigned long long ull;

__device__ __forceinline__ ull pack2(float a, float b) {
    ull r; asm("mov.b64 %0, {%1, %2};" : "=l"(r) : "f"(a), "f"(b)); return r;
}
__device__ __forceinline__ ull fma2(ull a, ull b, ull c) {
    ull d; asm("fma.rn.f32x2 %0, %1, %2, %3;" : "=l"(d) : "l"(a), "l"(b), "l"(c)); return d;
}
__device__ __forceinline__ void unpack2(ull v, float& lo, float& hi) {
    asm("mov.b64 {%0, %1}, %2;" : "=f"(lo), "=f"(hi) : "l"(v));
}

struct SmemLayout {
    float  sxa[NPTS];          // y-sorted db SoA                  16 KB
    float  sya[NPTS];          //                                  16 KB
    float  sza[NPTS];          //                                  16 KB
    float  swa[NPTS];          // |p|^2                            16 KB
    float4 qpts[QPB];          // y-sorted queries (x,y,z,|q|^2)   16 KB
    int    qidx[QPB];          //                                   4 KB
    int    dboff[NBIN + 1];    //                                   4 KB
    int    qoff[NBIN + 1];     //                                   4 KB
    int    cnt[NBIN];          //                                   4 KB
    int    cur[NBIN];          //                                   4 KB
    int    part[THREADS];      //                                   1 KB
    float  wmm[2][NWARP];
    float  redf[NWARP];
    float  ymin, ymax;
    bool   amlast;
};

// Tight vote-free scan: per 4 db pts: 4 LDS.128 + 12 FFMA2 + 8 FMNMX.
#define SCAN_RANGE(JLO, JHI)                                                   \
    _Pragma("unroll 2")                                                        \
    for (int j = (JLO); j < (JHI); j += 4) {                                   \
        const ulonglong2 Xv = *(const ulonglong2*)(s->sxa + j);                \
        const ulonglong2 Yv = *(const ulonglong2*)(s->sya + j);                \
        const ulonglong2 Zv = *(const ulonglong2*)(s->sza + j);                \
        const ulonglong2 Wv = *(const ulonglong2*)(s->swa + j);                \
        ull ta, tb; float e0, e1, f0, f1;                                      \
        ta = fma2(n00, Xv.x, Wv.x); ta = fma2(n10, Yv.x, ta); ta = fma2(n20, Zv.x, ta); \
        tb = fma2(n00, Xv.y, Wv.y); tb = fma2(n10, Yv.y, tb); tb = fma2(n20, Zv.y, tb); \
        unpack2(ta, e0, e1); unpack2(tb, f0, f1);                              \
        m00 = fminf(m00, e0); m00 = fminf(m00, f0);                            \
        m10 = fminf(m10, e1); m10 = fminf(m10, f1);                            \
        ta = fma2(n01, Xv.x, Wv.x); ta = fma2(n11, Yv.x, ta); ta = fma2(n21, Zv.x, ta); \
        tb = fma2(n01, Xv.y, Wv.y); tb = fma2(n11, Yv.y, tb); tb = fma2(n21, Zv.y, tb); \
        unpack2(ta, e0, e1); unpack2(tb, f0, f1);                              \
        m01 = fminf(m01, e0); m01 = fminf(m01, f0);                            \
        m11 = fminf(m11, e1); m11 = fminf(m11, f1);                            \
    }

__global__ __launch_bounds__(THREADS, 1) void chamfer_kernel(
    const float* __restrict__ x, const float* __restrict__ y,
    float* __restrict__ out)
{
    extern __shared__ char sraw[];
    SmemLayout* s = (SmemLayout*)sraw;

    const int tid = threadIdx.x;
    const int wid = tid >> 5, lid = tid & 31;
    const unsigned FULL = 0xFFFFFFFFu;
    const int dir = blockIdx.y;
    const int b   = blockIdx.z;
    const float* __restrict__ q  = (dir ? y : x) + (size_t)b * NPTS * 3
                                   + (size_t)blockIdx.x * QPB * 3;
    const float* __restrict__ db = (dir ? x : y) + (size_t)b * NPTS * 3;

    // ---- y min/max of db ----
    float lmin = FLT_MAX, lmax = -FLT_MAX;
    for (int j = tid; j < NPTS; j += THREADS) {
        float py = db[3 * j + 1];
        lmin = fminf(lmin, py); lmax = fmaxf(lmax, py);
    }
#pragma unroll
    for (int o = 16; o > 0; o >>= 1) {
        lmin = fminf(lmin, __shfl_xor_sync(FULL, lmin, o));
        lmax = fmaxf(lmax, __shfl_xor_sync(FULL, lmax, o));
    }
    if (lid == 0) { s->wmm[0][wid] = lmin; s->wmm[1][wid] = lmax; }
    for (int c = tid; c < NBIN; c += THREADS) s->cnt[c] = 0;
    __syncthreads();
    if (tid == 0) {
        float a0 = FLT_MAX, a1 = -FLT_MAX;
#pragma unroll
        for (int w = 0; w < NWARP; w++) {
            a0 = fminf(a0, s->wmm[0][w]); a1 = fmaxf(a1, s->wmm[1][w]);
        }
        s->ymin = a0; s->ymax = a1;
    }
    __syncthreads();

    const float ymin = s->ymin;
    const float W    = fmaxf((s->ymax - ymin) / NBIN, 1e-30f);
    const float inv  = 1.0f / W;

    // ---- db histogram by y-bin ----
    for (int j = tid; j < NPTS; j += THREADS) {
        float py = db[3 * j + 1];
        int c = min(max((int)((py - ymin) * inv), 0), NBIN - 1);
        atomicAdd(&s->cnt[c], 1);
    }
    __syncthreads();
    {   // scan -> dboff, cur
        const int base = tid * BPT;
        int sum = 0;
#pragma unroll
        for (int u = 0; u < BPT; u++) sum += s->cnt[base + u];
        s->part[tid] = sum;
        __syncthreads();
        for (int o = 1; o < THREADS; o <<= 1) {
            int v = (tid >= o) ? s->part[tid - o] : 0;
            __syncthreads();
            s->part[tid] += v;
            __syncthreads();
        }
        int run = (tid > 0) ? s->part[tid - 1] : 0;
#pragma unroll
        for (int u = 0; u < BPT; u++) {
            s->dboff[base + u] = run;
            s->cur[base + u]   = run;
            run += s->cnt[base + u];
        }
        if (tid == THREADS - 1) s->dboff[NBIN] = NPTS;
    }
    __syncthreads();
    // scatter db into SoA (intra-bin order cannot affect the final min value)
    for (int j = tid; j < NPTS; j += THREADS) {
        float a = db[3 * j], c = db[3 * j + 1], d = db[3 * j + 2];
        int cb = min(max((int)((c - ymin) * inv), 0), NBIN - 1);
        int pos = atomicAdd(&s->cur[cb], 1);
        s->sxa[pos] = a; s->sya[pos] = c; s->sza[pos] = d;
        s->swa[pos] = fmaf(a, a, fmaf(c, c, d * d));
    }
    __syncthreads();

    // ---- query histogram + scan + scatter + stable intra-bin fix ----
    for (int c = tid; c < NBIN; c += THREADS) s->cnt[c] = 0;
    __syncthreads();
    for (int j = tid; j < QPB; j += THREADS) {
        float py = q[3 * j + 1];
        int c = min(max((int)((py - ymin) * inv), 0), NBIN - 1);
        atomicAdd(&s->cnt[c], 1);
    }
    __syncthreads();
    {
        const int base = tid * BPT;
        int sum = 0;
#pragma unroll
        for (int u = 0; u < BPT; u++) sum += s->cnt[base + u];
        s->part[tid] = sum;
        __syncthreads();
        for (int o = 1; o < THREADS; o <<= 1) {
            int v = (tid >= o) ? s->part[tid - o] : 0;
            __syncthreads();
            s->part[tid] += v;
            __syncthreads();
        }
        int run = (tid > 0) ? s->part[tid - 1] : 0;
#pragma unroll
        for (int u = 0; u < BPT; u++) {
            s->qoff[base + u] = run;
            s->cur[base + u]  = run;
            run += s->cnt[base + u];
        }
        if (tid == THREADS - 1) s->qoff[NBIN] = QPB;
    }
    __syncthreads();
    for (int j = tid; j < QPB; j += THREADS) {
        float a = q[3 * j], c = q[3 * j + 1], d = q[3 * j + 2];
        int cb = min(max((int)((c - ymin) * inv), 0), NBIN - 1);
        int pos = atomicAdd(&s->cur[cb], 1);
        s->qpts[pos] = make_float4(a, c, d, fmaf(a, a, fmaf(c, c, d * d)));
        s->qidx[pos] = j;
    }
    __syncthreads();
    for (int c = tid; c < NBIN; c += THREADS) {   // stable fix (bins tiny)
        int lo = s->qoff[c], hi = s->qoff[c + 1];
        for (int i = lo + 1; i < hi; i++) {
            float4 pv = s->qpts[i]; int iv = s->qidx[i];
            int j2 = i - 1;
            while (j2 >= lo && s->qidx[j2] > iv) {
                s->qpts[j2 + 1] = s->qpts[j2];
                s->qidx[j2 + 1] = s->qidx[j2];
                j2--;
            }
            s->qpts[j2 + 1] = pv; s->qidx[j2 + 1] = iv;
        }
    }
    __syncthreads();

    // ---- Main: per warp-group of 64 sorted queries ----
    float ssum = 0.0f;
#pragma unroll 1
    for (int g = 0; g < GPW; g++) {
        const int base = (wid * GPW + g) * GSIZE;
        const float4 Q0 = s->qpts[base + 2 * lid];
        const float4 Q1 = s->qpts[base + 2 * lid + 1];
        const ull n00 = pack2(-2.0f * Q0.x, -2.0f * Q0.x);
        const ull n10 = pack2(-2.0f * Q0.y, -2.0f * Q0.y);
        const ull n20 = pack2(-2.0f * Q0.z, -2.0f * Q0.z);
        const ull n01 = pack2(-2.0f * Q1.x, -2.0f * Q1.x);
        const ull n11 = pack2(-2.0f * Q1.y, -2.0f * Q1.y);
        const ull n21 = pack2(-2.0f * Q1.z, -2.0f * Q1.z);
        float m00 = FLT_MAX, m10 = FLT_MAX, m01 = FLT_MAX, m11 = FLT_MAX;

        // Phase A: central slab (fixed 128 points around group's y-position)
        const float ylo_g = __shfl_sync(FULL, Q0.y, 0);
        const float yhi_g = __shfl_sync(FULL, Q1.y, 31);
        const float ymid  = 0.5f * (ylo_g + yhi_g);
        const int   cbin  = min(max((int)((ymid - ymin) * inv), 0), NBIN - 1);
        int lo_c = s->dboff[cbin] - CENT / 2;
        lo_c = min(max(lo_c, 0), NPTS - CENT) & ~3;
        const int hi_c = lo_c + CENT;
        SCAN_RANGE(lo_c, hi_c)

        // Upper bounds -> group window (computed once; 2-bin fp slack)
        const float d0 = sqrtf(fmaxf(fminf(m00, m10) + Q0.w, 0.0f));
        const float d1 = sqrtf(fmaxf(fminf(m01, m11) + Q1.w, 0.0f));
        float wlo = fminf(Q0.y - d0, Q1.y - d1);
        float whi = fmaxf(Q0.y + d0, Q1.y + d1);
#pragma unroll
        for (int o = 16; o > 0; o >>= 1) {
            wlo = fminf(wlo, __shfl_xor_sync(FULL, wlo, o));
            whi = fmaxf(whi, __shfl_xor_sync(FULL, whi, o));
        }
        const int lob = (int)fmaxf(floorf((wlo - ymin) * inv) - 2.0f, 0.0f);
        const int hib = (int)fminf(floorf((whi - ymin) * inv) + 2.0f, (float)(NBIN - 1));
        const int jlo = s->dboff[lob] & ~3;
        const int jhi = min((s->dboff[hib + 1] + 3) & ~3, NPTS);

        // Phase B: vote-free scan of the window outside the central slab
        const int preh = min(lo_c, jhi);
        SCAN_RANGE(jlo, preh)
        const int postl = max(hi_c, jlo);
        SCAN_RANGE(postl, jhi)

        ssum += fminf(m00, m10) + Q0.w + fminf(m01, m11) + Q1.w;
    }

    // ---- Block reduction (fixed order -> deterministic) ----
#pragma unroll
    for (int o = 16; o > 0; o >>= 1) ssum += __shfl_down_sync(FULL, ssum, o);
    if (lid == 0) s->redf[wid] = ssum;
    __syncthreads();
    if (tid == 0) {
        float t = 0.0f;
#pragma unroll
        for (int w = 0; w < NWARP; w++) t += s->redf[w];
        const int lin = blockIdx.x + SPLITS * (blockIdx.y + 2 * blockIdx.z);
        g_partial[lin] = t;
        __threadfence();
        unsigned int old = atomicAdd(&g_ticket, 1u);
        s->amlast = (old == NBLOCKS - 1);
    }
    __syncthreads();

    if (s->amlast) {
        float v = (tid < NBLOCKS) ? g_partial[tid] : 0.0f;
#pragma unroll
        for (int o = 16; o > 0; o >>= 1) v += __shfl_down_sync(FULL, v, o);
        if (lid == 0) s->redf[wid] = v;
        __syncthreads();
        if (tid == 0) {
            float t = 0.0f;
#pragma unroll
            for (int w = 0; w < NWARP; w++) t += s->redf[w];
            out[0] = t * (1.0f / ((float)NB * (float)NPTS));
            g_ticket = 0;   // reset for next graph replay
        }
    }
}

extern "C" void kernel_launch(void* const* d_in, const int* in_sizes, int n_in,
                              void* d_out, int out_size)
{
    const float* x = (const float*)d_in[0];
    const float* y = (const float*)d_in[1];
    float* out = (float*)d_out;

    const int smem = (int)sizeof(SmemLayout);   // ~101 KB
    cudaFuncSetAttribute(chamfer_kernel,
                         cudaFuncAttributeMaxDynamicSharedMemorySize, smem);

    dim3 grid(SPLITS, 2, NB);
    chamfer_kernel<<<grid, THREADS, smem>>>(x, y, out);
}

// round 11
// speedup vs baseline: 7.9499x; 1.1841x over previous
#include <cuda_runtime.h>
#include <cfloat>

// ChamferDistance: x,y = [16, 4096, 3] fp32 -> scalar
// R11 = R10 (precomputed-window lockstep NN) +
//   CENT=256 (tighter per-group NN upper bound -> smaller windows) +
//   dynamic per-warp group scheduling (shared atomic counter; fixes the
//   intra-block warp imbalance behind R10's issue=30%).
// Exact: d_ub is a real distance >= d_NN, so the y-window provably contains
// the true NN. Deterministic: group results are scatter-order independent,
// group->sum order fixed, query->lane assignment stabilized by intra-bin
// index sort.

#define NB      16
#define NPTS    4096
#define SPLITS  4
#define QPB     (NPTS / SPLITS)   // 1024 queries per block
#define THREADS 256
#define NWARP   (THREADS / 32)    // 8
#define GSIZE   64                // queries per group (2 per lane)
#define NGRPB   (QPB / GSIZE)     // 16 groups per block
#define NBLOCKS (NB * 2 * SPLITS) // 128
#define NBIN    1024
#define BPT     (NBIN / THREADS)  // 4
#define CENT    256               // central slab size (phase A)

__device__ float g_partial[NBLOCKS];
__device__ unsigned int g_ticket;   // zero-init; reset by last block each run

typedef unsigned long long ull;

__device__ __forceinline__ ull pack2(float a, float b) {
    ull r; asm("mov.b64 %0, {%1, %2};" : "=l"(r) : "f"(a), "f"(b)); return r;
}
__device__ __forceinline__ ull fma2(ull a, ull b, ull c) {
    ull d; asm("fma.rn.f32x2 %0, %1, %2, %3;" : "=l"(d) : "l"(a), "l"(b), "l"(c)); return d;
}
__device__ __forceinline__ void unpack2(ull v, float& lo, float& hi) {
    asm("mov.b64 {%0, %1}, %2;" : "=f"(lo), "=f"(hi) : "l"(v));
}

struct SmemLayout {
    float  sxa[NPTS];          // y-sorted db SoA                  16 KB
    float  sya[NPTS];          //                                  16 KB
    float  sza[NPTS];          //                                  16 KB
    float  swa[NPTS];          // |p|^2                            16 KB
    float4 qpts[QPB];          // y-sorted queries (x,y,z,|q|^2)   16 KB
    int    qidx[QPB];          //                                   4 KB
    int    dboff[NBIN + 1];
    int    qoff[NBIN + 1];
    int    cnt[NBIN];
    int    cur[NBIN];
    int    part[THREADS];
    float  gsum[NGRPB];        // per-group partial sums
    float  wmm[2][NWARP];
    float  ymin, ymax;
    int    gctr;               // dynamic group counter
    bool   amlast;
};

// Tight vote-free scan: per 4 db pts: 4 LDS.128 + 12 FFMA2 + 8 FMNMX.
#define SCAN_RANGE(JLO, JHI)                                                   \
    _Pragma("unroll 2")                                                        \
    for (int j = (JLO); j < (JHI); j += 4) {                                   \
        const ulonglong2 Xv = *(const ulonglong2*)(s->sxa + j);                \
        const ulonglong2 Yv = *(const ulonglong2*)(s->sya + j);                \
        const ulonglong2 Zv = *(const ulonglong2*)(s->sza + j);                \
        const ulonglong2 Wv = *(const ulonglong2*)(s->swa + j);                \
        ull ta, tb; float e0, e1, f0, f1;                                      \
        ta = fma2(n00, Xv.x, Wv.x); ta = fma2(n10, Yv.x, ta); ta = fma2(n20, Zv.x, ta); \
        tb = fma2(n00, Xv.y, Wv.y); tb = fma2(n10, Yv.y, tb); tb = fma2(n20, Zv.y, tb); \
        unpack2(ta, e0, e1); unpack2(tb, f0, f1);                              \
        m00 = fminf(m00, e0); m00 = fminf(m00, f0);                            \
        m10 = fminf(m10, e1); m10 = fminf(m10, f1);                            \
        ta = fma2(n01, Xv.x, Wv.x); ta = fma2(n11, Yv.x, ta); ta = fma2(n21, Zv.x, ta); \
        tb = fma2(n01, Xv.y, Wv.y); tb = fma2(n11, Yv.y, tb); tb = fma2(n21, Zv.y, tb); \
        unpack2(ta, e0, e1); unpack2(tb, f0, f1);                              \
        m01 = fminf(m01, e0); m01 = fminf(m01, f0);                            \
        m11 = fminf(m11, e1); m11 = fminf(m11, f1);                            \
    }

__global__ __launch_bounds__(THREADS, 1) void chamfer_kernel(
    const float* __restrict__ x, const float* __restrict__ y,
    float* __restrict__ out)
{
    extern __shared__ char sraw[];
    SmemLayout* s = (SmemLayout*)sraw;

    const int tid = threadIdx.x;
    const int wid = tid >> 5, lid = tid & 31;
    const unsigned FULL = 0xFFFFFFFFu;
    const int dir = blockIdx.y;
    const int b   = blockIdx.z;
    const float* __restrict__ q  = (dir ? y : x) + (size_t)b * NPTS * 3
                                   + (size_t)blockIdx.x * QPB * 3;
    const float* __restrict__ db = (dir ? x : y) + (size_t)b * NPTS * 3;

    // ---- y min/max of db ----
    float lmin = FLT_MAX, lmax = -FLT_MAX;
    for (int j = tid; j < NPTS; j += THREADS) {
        float py = db[3 * j + 1];
        lmin = fminf(lmin, py); lmax = fmaxf(lmax, py);
    }
#pragma unroll
    for (int o = 16; o > 0; o >>= 1) {
        lmin = fminf(lmin, __shfl_xor_sync(FULL, lmin, o));
        lmax = fmaxf(lmax, __shfl_xor_sync(FULL, lmax, o));
    }
    if (lid == 0) { s->wmm[0][wid] = lmin; s->wmm[1][wid] = lmax; }
    for (int c = tid; c < NBIN; c += THREADS) s->cnt[c] = 0;
    __syncthreads();
    if (tid == 0) {
        float a0 = FLT_MAX, a1 = -FLT_MAX;
#pragma unroll
        for (int w = 0; w < NWARP; w++) {
            a0 = fminf(a0, s->wmm[0][w]); a1 = fmaxf(a1, s->wmm[1][w]);
        }
        s->ymin = a0; s->ymax = a1;
        s->gctr = 0;
    }
    __syncthreads();

    const float ymin = s->ymin;
    const float W    = fmaxf((s->ymax - ymin) / NBIN, 1e-30f);
    const float inv  = 1.0f / W;

    // ---- db histogram by y-bin ----
    for (int j = tid; j < NPTS; j += THREADS) {
        float py = db[3 * j + 1];
        int c = min(max((int)((py - ymin) * inv), 0), NBIN - 1);
        atomicAdd(&s->cnt[c], 1);
    }
    __syncthreads();
    {   // scan -> dboff, cur
        const int base = tid * BPT;
        int sum = 0;
#pragma unroll
        for (int u = 0; u < BPT; u++) sum += s->cnt[base + u];
        s->part[tid] = sum;
        __syncthreads();
        for (int o = 1; o < THREADS; o <<= 1) {
            int v = (tid >= o) ? s->part[tid - o] : 0;
            __syncthreads();
            s->part[tid] += v;
            __syncthreads();
        }
        int run = (tid > 0) ? s->part[tid - 1] : 0;
#pragma unroll
        for (int u = 0; u < BPT; u++) {
            s->dboff[base + u] = run;
            s->cur[base + u]   = run;
            run += s->cnt[base + u];
        }
        if (tid == THREADS - 1) s->dboff[NBIN] = NPTS;
    }
    __syncthreads();
    // scatter db into SoA (intra-bin order cannot affect the final min value)
    for (int j = tid; j < NPTS; j += THREADS) {
        float a = db[3 * j], c = db[3 * j + 1], d = db[3 * j + 2];
        int cb = min(max((int)((c - ymin) * inv), 0), NBIN - 1);
        int pos = atomicAdd(&s->cur[cb], 1);
        s->sxa[pos] = a; s->sya[pos] = c; s->sza[pos] = d;
        s->swa[pos] = fmaf(a, a, fmaf(c, c, d * d));
    }
    __syncthreads();

    // ---- query histogram + scan + scatter + stable intra-bin fix ----
    for (int c = tid; c < NBIN; c += THREADS) s->cnt[c] = 0;
    __syncthreads();
    for (int j = tid; j < QPB; j += THREADS) {
        float py = q[3 * j + 1];
        int c = min(max((int)((py - ymin) * inv), 0), NBIN - 1);
        atomicAdd(&s->cnt[c], 1);
    }
    __syncthreads();
    {
        const int base = tid * BPT;
        int sum = 0;
#pragma unroll
        for (int u = 0; u < BPT; u++) sum += s->cnt[base + u];
        s->part[tid] = sum;
        __syncthreads();
        for (int o = 1; o < THREADS; o <<= 1) {
            int v = (tid >= o) ? s->part[tid - o] : 0;
            __syncthreads();
            s->part[tid] += v;
            __syncthreads();
        }
        int run = (tid > 0) ? s->part[tid - 1] : 0;
#pragma unroll
        for (int u = 0; u < BPT; u++) {
            s->qoff[base + u] = run;
            s->cur[base + u]  = run;
            run += s->cnt[base + u];
        }
        if (tid == THREADS - 1) s->qoff[NBIN] = QPB;
    }
    __syncthreads();
    for (int j = tid; j < QPB; j += THREADS) {
        float a = q[3 * j], c = q[3 * j + 1], d = q[3 * j + 2];
        int cb = min(max((int)((c - ymin) * inv), 0), NBIN - 1);
        int pos = atomicAdd(&s->cur[cb], 1);
        s->qpts[pos] = make_float4(a, c, d, fmaf(a, a, fmaf(c, c, d * d)));
        s->qidx[pos] = j;
    }
    __syncthreads();
    for (int c = tid; c < NBIN; c += THREADS) {   // stable fix (bins tiny)
        int lo = s->qoff[c], hi = s->qoff[c + 1];
        for (int i = lo + 1; i < hi; i++) {
            float4 pv = s->qpts[i]; int iv = s->qidx[i];
            int j2 = i - 1;
            while (j2 >= lo && s->qidx[j2] > iv) {
                s->qpts[j2 + 1] = s->qpts[j2];
                s->qidx[j2 + 1] = s->qidx[j2];
                j2--;
            }
            s->qpts[j2 + 1] = pv; s->qidx[j2 + 1] = iv;
        }
    }
    __syncthreads();

    // ---- Main: dynamic group scheduling (16 groups of 64 sorted queries) ----
    while (true) {
        int g = 0;
        if (lid == 0) g = atomicAdd(&s->gctr, 1);
        g = __shfl_sync(FULL, g, 0);
        if (g >= NGRPB) break;

        const int base = g * GSIZE;
        const float4 Q0 = s->qpts[base + 2 * lid];
        const float4 Q1 = s->qpts[base + 2 * lid + 1];
        const ull n00 = pack2(-2.0f * Q0.x, -2.0f * Q0.x);
        const ull n10 = pack2(-2.0f * Q0.y, -2.0f * Q0.y);
        const ull n20 = pack2(-2.0f * Q0.z, -2.0f * Q0.z);
        const ull n01 = pack2(-2.0f * Q1.x, -2.0f * Q1.x);
        const ull n11 = pack2(-2.0f * Q1.y, -2.0f * Q1.y);
        const ull n21 = pack2(-2.0f * Q1.z, -2.0f * Q1.z);
        float m00 = FLT_MAX, m10 = FLT_MAX, m01 = FLT_MAX, m11 = FLT_MAX;

        // Phase A: central slab of CENT points around group's y-position
        const float ylo_g = __shfl_sync(FULL, Q0.y, 0);
        const float yhi_g = __shfl_sync(FULL, Q1.y, 31);
        const float ymid  = 0.5f * (ylo_g + yhi_g);
        const int   cbin  = min(max((int)((ymid - ymin) * inv), 0), NBIN - 1);
        int lo_c = s->dboff[cbin] - CENT / 2;
        lo_c = min(max(lo_c, 0), NPTS - CENT) & ~3;
        const int hi_c = lo_c + CENT;
        SCAN_RANGE(lo_c, hi_c)

        // Upper bounds -> group window (computed once; 2-bin fp slack)
        const float d0 = sqrtf(fmaxf(fminf(m00, m10) + Q0.w, 0.0f));
        const float d1 = sqrtf(fmaxf(fminf(m01, m11) + Q1.w, 0.0f));
        float wlo = fminf(Q0.y - d0, Q1.y - d1);
        float whi = fmaxf(Q0.y + d0, Q1.y + d1);
#pragma unroll
        for (int o = 16; o > 0; o >>= 1) {
            wlo = fminf(wlo, __shfl_xor_sync(FULL, wlo, o));
            whi = fmaxf(whi, __shfl_xor_sync(FULL, whi, o));
        }
        const int lob = (int)fmaxf(floorf((wlo - ymin) * inv) - 2.0f, 0.0f);
        const int hib = (int)fminf(floorf((whi - ymin) * inv) + 2.0f, (float)(NBIN - 1));
        const int jlo = s->dboff[lob] & ~3;
        const int jhi = min((s->dboff[hib + 1] + 3) & ~3, NPTS);

        // Phase B: vote-free scan of the window outside the central slab
        const int preh = min(lo_c, jhi);
        SCAN_RANGE(jlo, preh)
        const int postl = max(hi_c, jlo);
        SCAN_RANGE(postl, jhi)

        // Warp-reduce this group's sum (fixed shuffle order) -> fixed slot
        float v = fminf(m00, m10) + Q0.w + fminf(m01, m11) + Q1.w;
#pragma unroll
        for (int o = 16; o > 0; o >>= 1) v += __shfl_down_sync(FULL, v, o);
        if (lid == 0) s->gsum[g] = v;
    }
    __syncthreads();

    // ---- Block partial: fixed-order sum of group sums ----
    if (tid == 0) {
        float t = 0.0f;
#pragma unroll
        for (int g = 0; g < NGRPB; g++) t += s->gsum[g];
        const int lin = blockIdx.x + SPLITS * (blockIdx.y + 2 * blockIdx.z);
        g_partial[lin] = t;
        __threadfence();
        unsigned int old = atomicAdd(&g_ticket, 1u);
        s->amlast = (old == NBLOCKS - 1);
    }
    __syncthreads();

    // ---- Last block: reduce all 128 partials in fixed order ----
    if (s->amlast) {
        float v = (tid < NBLOCKS) ? g_partial[tid] : 0.0f;
#pragma unroll
        for (int o = 16; o > 0; o >>= 1) v += __shfl_down_sync(FULL, v, o);
        __shared__ float wred[NWARP];
        if (lid == 0) wred[wid] = v;
        __syncthreads();
        if (tid == 0) {
            float t = 0.0f;
#pragma unroll
            for (int w = 0; w < NWARP; w++) t += wred[w];
            out[0] = t * (1.0f / ((float)NB * (float)NPTS));
            g_ticket = 0;   // reset for next graph replay
        }
    }
}

extern "C" void kernel_launch(void* const* d_in, const int* in_sizes, int n_in,
                              void* d_out, int out_size)
{
    const float* x = (const float*)d_in[0];
    const float* y = (const float*)d_in[1];
    float* out = (float*)d_out;

    const int smem = (int)sizeof(SmemLayout);   // ~101 KB
    cudaFuncSetAttribute(chamfer_kernel,
                         cudaFuncAttributeMaxDynamicSharedMemorySize, smem);

    dim3 grid(SPLITS, 2, NB);
    chamfer_kernel<<<grid, THREADS, smem>>>(x, y, out);
}

// round 12
// speedup vs baseline: 8.3112x; 1.0455x over previous
#include <cuda_runtime.h>
#include <cfloat>

// ChamferDistance: x,y = [16, 4096, 3] fp32 -> scalar
// R12 = R11 (y-sorted precomputed-window lockstep NN, CENT=256, dynamic
//       groups) with THREADS 256 -> 512: 16 warps/SM = 4 warps/SMSP to cover
//       the scan-loop latency behind R11's issue=29.6%.

#define NB      16
#define NPTS    4096
#define SPLITS  4
#define QPB     (NPTS / SPLITS)   // 1024 queries per block
#define THREADS 512
#define NWARP   (THREADS / 32)    // 16
#define GSIZE   64                // queries per group (2 per lane)
#define NGRPB   (QPB / GSIZE)     // 16 groups per block
#define NBLOCKS (NB * 2 * SPLITS) // 128
#define NBIN    1024
#define BPT     (NBIN / THREADS)  // 2
#define CENT    256               // central slab size (phase A)

__device__ float g_partial[NBLOCKS];
__device__ unsigned int g_ticket;   // zero-init; reset by last block each run

typedef unsigned long long ull;

__device__ __forceinline__ ull pack2(float a, float b) {
    ull r; asm("mov.b64 %0, {%1, %2};" : "=l"(r) : "f"(a), "f"(b)); return r;
}
__device__ __forceinline__ ull fma2(ull a, ull b, ull c) {
    ull d; asm("fma.rn.f32x2 %0, %1, %2, %3;" : "=l"(d) : "l"(a), "l"(b), "l"(c)); return d;
}
__device__ __forceinline__ void unpack2(ull v, float& lo, float& hi) {
    asm("mov.b64 {%0, %1}, %2;" : "=f"(lo), "=f"(hi) : "l"(v));
}

struct SmemLayout {
    float  sxa[NPTS];          // y-sorted db SoA                  16 KB
    float  sya[NPTS];          //                                  16 KB
    float  sza[NPTS];          //                                  16 KB
    float  swa[NPTS];          // |p|^2                            16 KB
    float4 qpts[QPB];          // y-sorted queries (x,y,z,|q|^2)   16 KB
    int    qidx[QPB];          //                                   4 KB
    int    dboff[NBIN + 1];
    int    qoff[NBIN + 1];
    int    cnt[NBIN];
    int    cur[NBIN];
    int    part[THREADS];
    float  gsum[NGRPB];        // per-group partial sums
    float  wmm[2][NWARP];
    float  ymin, ymax;
    int    gctr;               // dynamic group counter
    bool   amlast;
};

// Tight vote-free scan: per 4 db pts: 4 LDS.128 + 12 FFMA2 + 8 FMNMX.
#define SCAN_RANGE(JLO, JHI)                                                   \
    _Pragma("unroll 2")                                                        \
    for (int j = (JLO); j < (JHI); j += 4) {                                   \
        const ulonglong2 Xv = *(const ulonglong2*)(s->sxa + j);                \
        const ulonglong2 Yv = *(const ulonglong2*)(s->sya + j);                \
        const ulonglong2 Zv = *(const ulonglong2*)(s->sza + j);                \
        const ulonglong2 Wv = *(const ulonglong2*)(s->swa + j);                \
        ull ta, tb; float e0, e1, f0, f1;                                      \
        ta = fma2(n00, Xv.x, Wv.x); ta = fma2(n10, Yv.x, ta); ta = fma2(n20, Zv.x, ta); \
        tb = fma2(n00, Xv.y, Wv.y); tb = fma2(n10, Yv.y, tb); tb = fma2(n20, Zv.y, tb); \
        unpack2(ta, e0, e1); unpack2(tb, f0, f1);                              \
        m00 = fminf(m00, e0); m00 = fminf(m00, f0);                            \
        m10 = fminf(m10, e1); m10 = fminf(m10, f1);                            \
        ta = fma2(n01, Xv.x, Wv.x); ta = fma2(n11, Yv.x, ta); ta = fma2(n21, Zv.x, ta); \
        tb = fma2(n01, Xv.y, Wv.y); tb = fma2(n11, Yv.y, tb); tb = fma2(n21, Zv.y, tb); \
        unpack2(ta, e0, e1); unpack2(tb, f0, f1);                              \
        m01 = fminf(m01, e0); m01 = fminf(m01, f0);                            \
        m11 = fminf(m11, e1); m11 = fminf(m11, f1);                            \
    }

__global__ __launch_bounds__(THREADS, 1) void chamfer_kernel(
    const float* __restrict__ x, const float* __restrict__ y,
    float* __restrict__ out)
{
    extern __shared__ char sraw[];
    SmemLayout* s = (SmemLayout*)sraw;

    const int tid = threadIdx.x;
    const int wid = tid >> 5, lid = tid & 31;
    const unsigned FULL = 0xFFFFFFFFu;
    const int dir = blockIdx.y;
    const int b   = blockIdx.z;
    const float* __restrict__ q  = (dir ? y : x) + (size_t)b * NPTS * 3
                                   + (size_t)blockIdx.x * QPB * 3;
    const float* __restrict__ db = (dir ? x : y) + (size_t)b * NPTS * 3;

    // ---- y min/max of db ----
    float lmin = FLT_MAX, lmax = -FLT_MAX;
    for (int j = tid; j < NPTS; j += THREADS) {
        float py = db[3 * j + 1];
        lmin = fminf(lmin, py); lmax = fmaxf(lmax, py);
    }
#pragma unroll
    for (int o = 16; o > 0; o >>= 1) {
        lmin = fminf(lmin, __shfl_xor_sync(FULL, lmin, o));
        lmax = fmaxf(lmax, __shfl_xor_sync(FULL, lmax, o));
    }
    if (lid == 0) { s->wmm[0][wid] = lmin; s->wmm[1][wid] = lmax; }
    for (int c = tid; c < NBIN; c += THREADS) s->cnt[c] = 0;
    __syncthreads();
    if (tid == 0) {
        float a0 = FLT_MAX, a1 = -FLT_MAX;
#pragma unroll
        for (int w = 0; w < NWARP; w++) {
            a0 = fminf(a0, s->wmm[0][w]); a1 = fmaxf(a1, s->wmm[1][w]);
        }
        s->ymin = a0; s->ymax = a1;
        s->gctr = 0;
    }
    __syncthreads();

    const float ymin = s->ymin;
    const float W    = fmaxf((s->ymax - ymin) / NBIN, 1e-30f);
    const float inv  = 1.0f / W;

    // ---- db histogram by y-bin ----
    for (int j = tid; j < NPTS; j += THREADS) {
        float py = db[3 * j + 1];
        int c = min(max((int)((py - ymin) * inv), 0), NBIN - 1);
        atomicAdd(&s->cnt[c], 1);
    }
    __syncthreads();
    {   // scan -> dboff, cur
        const int base = tid * BPT;
        int sum = 0;
#pragma unroll
        for (int u = 0; u < BPT; u++) sum += s->cnt[base + u];
        s->part[tid] = sum;
        __syncthreads();
        for (int o = 1; o < THREADS; o <<= 1) {
            int v = (tid >= o) ? s->part[tid - o] : 0;
            __syncthreads();
            s->part[tid] += v;
            __syncthreads();
        }
        int run = (tid > 0) ? s->part[tid - 1] : 0;
#pragma unroll
        for (int u = 0; u < BPT; u++) {
            s->dboff[base + u] = run;
            s->cur[base + u]   = run;
            run += s->cnt[base + u];
        }
        if (tid == THREADS - 1) s->dboff[NBIN] = NPTS;
    }
    __syncthreads();
    // scatter db into SoA (intra-bin order cannot affect the final min value)
    for (int j = tid; j < NPTS; j += THREADS) {
        float a = db[3 * j], c = db[3 * j + 1], d = db[3 * j + 2];
        int cb = min(max((int)((c - ymin) * inv), 0), NBIN - 1);
        int pos = atomicAdd(&s->cur[cb], 1);
        s->sxa[pos] = a; s->sya[pos] = c; s->sza[pos] = d;
        s->swa[pos] = fmaf(a, a, fmaf(c, c, d * d));
    }
    __syncthreads();

    // ---- query histogram + scan + scatter + stable intra-bin fix ----
    for (int c = tid; c < NBIN; c += THREADS) s->cnt[c] = 0;
    __syncthreads();
    for (int j = tid; j < QPB; j += THREADS) {
        float py = q[3 * j + 1];
        int c = min(max((int)((py - ymin) * inv), 0), NBIN - 1);
        atomicAdd(&s->cnt[c], 1);
    }
    __syncthreads();
    {
        const int base = tid * BPT;
        int sum = 0;
#pragma unroll
        for (int u = 0; u < BPT; u++) sum += s->cnt[base + u];
        s->part[tid] = sum;
        __syncthreads();
        for (int o = 1; o < THREADS; o <<= 1) {
            int v = (tid >= o) ? s->part[tid - o] : 0;
            __syncthreads();
            s->part[tid] += v;
            __syncthreads();
        }
        int run = (tid > 0) ? s->part[tid - 1] : 0;
#pragma unroll
        for (int u = 0; u < BPT; u++) {
            s->qoff[base + u] = run;
            s->cur[base + u]  = run;
            run += s->cnt[base + u];
        }
        if (tid == THREADS - 1) s->qoff[NBIN] = QPB;
    }
    __syncthreads();
    for (int j = tid; j < QPB; j += THREADS) {
        float a = q[3 * j], c = q[3 * j + 1], d = q[3 * j + 2];
        int cb = min(max((int)((c - ymin) * inv), 0), NBIN - 1);
        int pos = atomicAdd(&s->cur[cb], 1);
        s->qpts[pos] = make_float4(a, c, d, fmaf(a, a, fmaf(c, c, d * d)));
        s->qidx[pos] = j;
    }
    __syncthreads();
    for (int c = tid; c < NBIN; c += THREADS) {   // stable fix (bins tiny)
        int lo = s->qoff[c], hi = s->qoff[c + 1];
        for (int i = lo + 1; i < hi; i++) {
            float4 pv = s->qpts[i]; int iv = s->qidx[i];
            int j2 = i - 1;
            while (j2 >= lo && s->qidx[j2] > iv) {
                s->qpts[j2 + 1] = s->qpts[j2];
                s->qidx[j2 + 1] = s->qidx[j2];
                j2--;
            }
            s->qpts[j2 + 1] = pv; s->qidx[j2 + 1] = iv;
        }
    }
    __syncthreads();

    // ---- Main: dynamic group scheduling (16 groups of 64 sorted queries) ----
    while (true) {
        int g = 0;
        if (lid == 0) g = atomicAdd(&s->gctr, 1);
        g = __shfl_sync(FULL, g, 0);
        if (g >= NGRPB) break;

        const int base = g * GSIZE;
        const float4 Q0 = s->qpts[base + 2 * lid];
        const float4 Q1 = s->qpts[base + 2 * lid + 1];
        const ull n00 = pack2(-2.0f * Q0.x, -2.0f * Q0.x);
        const ull n10 = pack2(-2.0f * Q0.y, -2.0f * Q0.y);
        const ull n20 = pack2(-2.0f * Q0.z, -2.0f * Q0.z);
        const ull n01 = pack2(-2.0f * Q1.x, -2.0f * Q1.x);
        const ull n11 = pack2(-2.0f * Q1.y, -2.0f * Q1.y);
        const ull n21 = pack2(-2.0f * Q1.z, -2.0f * Q1.z);
        float m00 = FLT_MAX, m10 = FLT_MAX, m01 = FLT_MAX, m11 = FLT_MAX;

        // Phase A: central slab of CENT points around group's y-position
        const float ylo_g = __shfl_sync(FULL, Q0.y, 0);
        const float yhi_g = __shfl_sync(FULL, Q1.y, 31);
        const float ymid  = 0.5f * (ylo_g + yhi_g);
        const int   cbin  = min(max((int)((ymid - ymin) * inv), 0), NBIN - 1);
        int lo_c = s->dboff[cbin] - CENT / 2;
        lo_c = min(max(lo_c, 0), NPTS - CENT) & ~3;
        const int hi_c = lo_c + CENT;
        SCAN_RANGE(lo_c, hi_c)

        // Upper bounds -> group window (computed once; 2-bin fp slack)
        const float d0 = sqrtf(fmaxf(fminf(m00, m10) + Q0.w, 0.0f));
        const float d1 = sqrtf(fmaxf(fminf(m01, m11) + Q1.w, 0.0f));
        float wlo = fminf(Q0.y - d0, Q1.y - d1);
        float whi = fmaxf(Q0.y + d0, Q1.y + d1);
#pragma unroll
        for (int o = 16; o > 0; o >>= 1) {
            wlo = fminf(wlo, __shfl_xor_sync(FULL, wlo, o));
            whi = fmaxf(whi, __shfl_xor_sync(FULL, whi, o));
        }
        const int lob = (int)fmaxf(floorf((wlo - ymin) * inv) - 2.0f, 0.0f);
        const int hib = (int)fminf(floorf((whi - ymin) * inv) + 2.0f, (float)(NBIN - 1));
        const int jlo = s->dboff[lob] & ~3;
        const int jhi = min((s->dboff[hib + 1] + 3) & ~3, NPTS);

        // Phase B: vote-free scan of the window outside the central slab
        const int preh = min(lo_c, jhi);
        SCAN_RANGE(jlo, preh)
        const int postl = max(hi_c, jlo);
        SCAN_RANGE(postl, jhi)

        // Warp-reduce this group's sum (fixed shuffle order) -> fixed slot
        float v = fminf(m00, m10) + Q0.w + fminf(m01, m11) + Q1.w;
#pragma unroll
        for (int o = 16; o > 0; o >>= 1) v += __shfl_down_sync(FULL, v, o);
        if (lid == 0) s->gsum[g] = v;
    }
    __syncthreads();

    // ---- Block partial: fixed-order sum of group sums ----
    if (tid == 0) {
        float t = 0.0f;
#pragma unroll
        for (int g = 0; g < NGRPB; g++) t += s->gsum[g];
        const int lin = blockIdx.x + SPLITS * (blockIdx.y + 2 * blockIdx.z);
        g_partial[lin] = t;
        __threadfence();
        unsigned int old = atomicAdd(&g_ticket, 1u);
        s->amlast = (old == NBLOCKS - 1);
    }
    __syncthreads();

    // ---- Last block: reduce all 128 partials in fixed order ----
    if (s->amlast) {
        float v = (tid < NBLOCKS) ? g_partial[tid] : 0.0f;
#pragma unroll
        for (int o = 16; o > 0; o >>= 1) v += __shfl_down_sync(FULL, v, o);
        __shared__ float wred[NWARP];
        if (lid == 0) wred[wid] = v;
        __syncthreads();
        if (tid == 0) {
            float t = 0.0f;
#pragma unroll
            for (int w = 0; w < NWARP; w++) t += wred[w];
            out[0] = t * (1.0f / ((float)NB * (float)NPTS));
            g_ticket = 0;   // reset for next graph replay
        }
    }
}

extern "C" void kernel_launch(void* const* d_in, const int* in_sizes, int n_in,
                              void* d_out, int out_size)
{
    const float* x = (const float*)d_in[0];
    const float* y = (const float*)d_in[1];
    float* out = (float*)d_out;

    const int smem = (int)sizeof(SmemLayout);   // ~101 KB
    cudaFuncSetAttribute(chamfer_kernel,
                         cudaFuncAttributeMaxDynamicSharedMemorySize, smem);

    dim3 grid(SPLITS, 2, NB);
    chamfer_kernel<<<grid, THREADS, smem>>>(x, y, out);
}

// round 13
// speedup vs baseline: 10.4889x; 1.2620x over previous
#include <cuda_runtime.h>
#include <cfloat>

// ChamferDistance: x,y = [16, 4096, 3] fp32 -> scalar
// R13 = R12 (y-sorted precomputed-window lockstep NN, CENT=256) with the main
//       phase restructured as a chunked work queue: per-group windows are
//       split into 512-pt chunks that all 16 warps grab dynamically, merging
//       per-query results via order-preserving atomicMin. Converts block time
//       from max(window) to mean(window) (R12's tail imbalance).

#define NB      16
#define NPTS    4096
#define SPLITS  4
#define QPB     (NPTS / SPLITS)   // 1024 queries per block
#define THREADS 512
#define NWARP   (THREADS / 32)    // 16
#define GSIZE   64                // queries per group (2 per lane)
#define NGRPB   (QPB / GSIZE)     // 16 groups per block (== NWARP)
#define NBLOCKS (NB * 2 * SPLITS) // 128
#define NBIN    1024
#define BPT     (NBIN / THREADS)  // 2
#define CENT    256               // central slab size (stage A)
#define CHUNK   512               // scan chunk size (stage B)
#define MAXCH   256               // queue capacity (worst case 128+32)

__device__ float g_partial[NBLOCKS];
__device__ unsigned int g_ticket;   // zero-init; reset by last block each run

typedef unsigned long long ull;

__device__ __forceinline__ ull pack2(float a, float b) {
    ull r; asm("mov.b64 %0, {%1, %2};" : "=l"(r) : "f"(a), "f"(b)); return r;
}
__device__ __forceinline__ ull fma2(ull a, ull b, ull c) {
    ull d; asm("fma.rn.f32x2 %0, %1, %2, %3;" : "=l"(d) : "l"(a), "l"(b), "l"(c)); return d;
}
__device__ __forceinline__ void unpack2(ull v, float& lo, float& hi) {
    asm("mov.b64 {%0, %1}, %2;" : "=f"(lo), "=f"(hi) : "l"(v));
}
// Order-preserving float<->uint map (valid for all floats incl. negatives).
__device__ __forceinline__ unsigned int fenc(float f) {
    unsigned int u = __float_as_uint(f);
    return u ^ (((int)u >> 31) | 0x80000000u);
}
__device__ __forceinline__ float fdec(unsigned int e) {
    unsigned int u = (e & 0x80000000u) ? (e ^ 0x80000000u) : ~e;
    return __uint_as_float(u);
}

struct SmemLayout {
    float  sxa[NPTS];          // y-sorted db SoA                  16 KB
    float  sya[NPTS];
    float  sza[NPTS];
    float  swa[NPTS];          // |p|^2
    float4 qpts[QPB];          // y-sorted queries (x,y,z,|q|^2)   16 KB
    int    qidx[QPB];
    unsigned int gdist[QPB];   // per-query encoded min distance    4 KB
    int    dboff[NBIN + 1];
    int    qoff[NBIN + 1];
    int    cnt[NBIN];
    int    cur[NBIN];
    int    part[THREADS];
    int    cg[MAXCH];          // chunk -> group
    int    clo[MAXCH], chi[MAXCH];
    float  wmm[2][NWARP];
    float  wred[NWARP];
    float  ymin, ymax;
    int    nch;                // number of queued chunks
    int    cctr;               // dynamic chunk counter
    bool   amlast;
};

// Tight vote-free scan: per 4 db pts: 4 LDS.128 + 12 FFMA2 + 8 FMNMX.
#define SCAN_RANGE(JLO, JHI)                                                   \
    _Pragma("unroll 2")                                                        \
    for (int j = (JLO); j < (JHI); j += 4) {                                   \
        const ulonglong2 Xv = *(const ulonglong2*)(s->sxa + j);                \
        const ulonglong2 Yv = *(const ulonglong2*)(s->sya + j);                \
        const ulonglong2 Zv = *(const ulonglong2*)(s->sza + j);                \
        const ulonglong2 Wv = *(const ulonglong2*)(s->swa + j);                \
        ull ta, tb; float e0, e1, f0, f1;                                      \
        ta = fma2(n00, Xv.x, Wv.x); ta = fma2(n10, Yv.x, ta); ta = fma2(n20, Zv.x, ta); \
        tb = fma2(n00, Xv.y, Wv.y); tb = fma2(n10, Yv.y, tb); tb = fma2(n20, Zv.y, tb); \
        unpack2(ta, e0, e1); unpack2(tb, f0, f1);                              \
        m00 = fminf(m00, e0); m00 = fminf(m00, f0);                            \
        m10 = fminf(m10, e1); m10 = fminf(m10, f1);                            \
        ta = fma2(n01, Xv.x, Wv.x); ta = fma2(n11, Yv.x, ta); ta = fma2(n21, Zv.x, ta); \
        tb = fma2(n01, Xv.y, Wv.y); tb = fma2(n11, Yv.y, tb); tb = fma2(n21, Zv.y, tb); \
        unpack2(ta, e0, e1); unpack2(tb, f0, f1);                              \
        m01 = fminf(m01, e0); m01 = fminf(m01, f0);                            \
        m11 = fminf(m11, e1); m11 = fminf(m11, f1);                            \
    }

__global__ __launch_bounds__(THREADS, 1) void chamfer_kernel(
    const float* __restrict__ x, const float* __restrict__ y,
    float* __restrict__ out)
{
    extern __shared__ char sraw[];
    SmemLayout* s = (SmemLayout*)sraw;

    const int tid = threadIdx.x;
    const int wid = tid >> 5, lid = tid & 31;
    const unsigned FULL = 0xFFFFFFFFu;
    const int dir = blockIdx.y;
    const int b   = blockIdx.z;
    const float* __restrict__ q  = (dir ? y : x) + (size_t)b * NPTS * 3
                                   + (size_t)blockIdx.x * QPB * 3;
    const float* __restrict__ db = (dir ? x : y) + (size_t)b * NPTS * 3;

    // ---- y min/max of db ----
    float lmin = FLT_MAX, lmax = -FLT_MAX;
    for (int j = tid; j < NPTS; j += THREADS) {
        float py = db[3 * j + 1];
        lmin = fminf(lmin, py); lmax = fmaxf(lmax, py);
    }
#pragma unroll
    for (int o = 16; o > 0; o >>= 1) {
        lmin = fminf(lmin, __shfl_xor_sync(FULL, lmin, o));
        lmax = fmaxf(lmax, __shfl_xor_sync(FULL, lmax, o));
    }
    if (lid == 0) { s->wmm[0][wid] = lmin; s->wmm[1][wid] = lmax; }
    for (int c = tid; c < NBIN; c += THREADS) s->cnt[c] = 0;
    const unsigned ENC_MAX = fenc(FLT_MAX);
    for (int i = tid; i < QPB; i += THREADS) s->gdist[i] = ENC_MAX;
    __syncthreads();
    if (tid == 0) {
        float a0 = FLT_MAX, a1 = -FLT_MAX;
#pragma unroll
        for (int w = 0; w < NWARP; w++) {
            a0 = fminf(a0, s->wmm[0][w]); a1 = fmaxf(a1, s->wmm[1][w]);
        }
        s->ymin = a0; s->ymax = a1;
        s->nch = 0; s->cctr = 0;
    }
    __syncthreads();

    const float ymin = s->ymin;
    const float W    = fmaxf((s->ymax - ymin) / NBIN, 1e-30f);
    const float inv  = 1.0f / W;

    // ---- db histogram by y-bin ----
    for (int j = tid; j < NPTS; j += THREADS) {
        float py = db[3 * j + 1];
        int c = min(max((int)((py - ymin) * inv), 0), NBIN - 1);
        atomicAdd(&s->cnt[c], 1);
    }
    __syncthreads();
    {   // scan -> dboff, cur
        const int base = tid * BPT;
        int sum = 0;
#pragma unroll
        for (int u = 0; u < BPT; u++) sum += s->cnt[base + u];
        s->part[tid] = sum;
        __syncthreads();
        for (int o = 1; o < THREADS; o <<= 1) {
            int v = (tid >= o) ? s->part[tid - o] : 0;
            __syncthreads();
            s->part[tid] += v;
            __syncthreads();
        }
        int run = (tid > 0) ? s->part[tid - 1] : 0;
#pragma unroll
        for (int u = 0; u < BPT; u++) {
            s->dboff[base + u] = run;
            s->cur[base + u]   = run;
            run += s->cnt[base + u];
        }
        if (tid == THREADS - 1) s->dboff[NBIN] = NPTS;
    }
    __syncthreads();
    // scatter db into SoA (intra-bin order cannot affect the final min value)
    for (int j = tid; j < NPTS; j += THREADS) {
        float a = db[3 * j], c = db[3 * j + 1], d = db[3 * j + 2];
        int cb = min(max((int)((c - ymin) * inv), 0), NBIN - 1);
        int pos = atomicAdd(&s->cur[cb], 1);
        s->sxa[pos] = a; s->sya[pos] = c; s->sza[pos] = d;
        s->swa[pos] = fmaf(a, a, fmaf(c, c, d * d));
    }
    __syncthreads();

    // ---- query histogram + scan + scatter + stable intra-bin fix ----
    for (int c = tid; c < NBIN; c += THREADS) s->cnt[c] = 0;
    __syncthreads();
    for (int j = tid; j < QPB; j += THREADS) {
        float py = q[3 * j + 1];
        int c = min(max((int)((py - ymin) * inv), 0), NBIN - 1);
        atomicAdd(&s->cnt[c], 1);
    }
    __syncthreads();
    {
        const int base = tid * BPT;
        int sum = 0;
#pragma unroll
        for (int u = 0; u < BPT; u++) sum += s->cnt[base + u];
        s->part[tid] = sum;
        __syncthreads();
        for (int o = 1; o < THREADS; o <<= 1) {
            int v = (tid >= o) ? s->part[tid - o] : 0;
            __syncthreads();
            s->part[tid] += v;
            __syncthreads();
        }
        int run = (tid > 0) ? s->part[tid - 1] : 0;
#pragma unroll
        for (int u = 0; u < BPT; u++) {
            s->qoff[base + u] = run;
            s->cur[base + u]  = run;
            run += s->cnt[base + u];
        }
        if (tid == THREADS - 1) s->qoff[NBIN] = QPB;
    }
    __syncthreads();
    for (int j = tid; j < QPB; j += THREADS) {
        float a = q[3 * j], c = q[3 * j + 1], d = q[3 * j + 2];
        int cb = min(max((int)((c - ymin) * inv), 0), NBIN - 1);
        int pos = atomicAdd(&s->cur[cb], 1);
        s->qpts[pos] = make_float4(a, c, d, fmaf(a, a, fmaf(c, c, d * d)));
        s->qidx[pos] = j;
    }
    __syncthreads();
    for (int c = tid; c < NBIN; c += THREADS) {   // stable fix (bins tiny)
        int lo = s->qoff[c], hi = s->qoff[c + 1];
        for (int i = lo + 1; i < hi; i++) {
            float4 pv = s->qpts[i]; int iv = s->qidx[i];
            int j2 = i - 1;
            while (j2 >= lo && s->qidx[j2] > iv) {
                s->qpts[j2 + 1] = s->qpts[j2];
                s->qidx[j2 + 1] = s->qidx[j2];
                j2--;
            }
            s->qpts[j2 + 1] = pv; s->qidx[j2 + 1] = iv;
        }
    }
    __syncthreads();

    // ---- Stage A: warp w handles group w's slab + window + enqueue ----
    {
        const int g = wid;               // NWARP == NGRPB
        const int base = g * GSIZE;
        const float4 Q0 = s->qpts[base + 2 * lid];
        const float4 Q1 = s->qpts[base + 2 * lid + 1];
        const ull n00 = pack2(-2.0f * Q0.x, -2.0f * Q0.x);
        const ull n10 = pack2(-2.0f * Q0.y, -2.0f * Q0.y);
        const ull n20 = pack2(-2.0f * Q0.z, -2.0f * Q0.z);
        const ull n01 = pack2(-2.0f * Q1.x, -2.0f * Q1.x);
        const ull n11 = pack2(-2.0f * Q1.y, -2.0f * Q1.y);
        const ull n21 = pack2(-2.0f * Q1.z, -2.0f * Q1.z);
        float m00 = FLT_MAX, m10 = FLT_MAX, m01 = FLT_MAX, m11 = FLT_MAX;

        const float ylo_g = __shfl_sync(FULL, Q0.y, 0);
        const float yhi_g = __shfl_sync(FULL, Q1.y, 31);
        const float ymid  = 0.5f * (ylo_g + yhi_g);
        const int   cbin  = min(max((int)((ymid - ymin) * inv), 0), NBIN - 1);
        int lo_c = s->dboff[cbin] - CENT / 2;
        lo_c = min(max(lo_c, 0), NPTS - CENT) & ~3;
        const int hi_c = lo_c + CENT;
        SCAN_RANGE(lo_c, hi_c)

        // merge slab results
        const float da = fminf(m00, m10) + Q0.w;
        const float dbq = fminf(m01, m11) + Q1.w;
        atomicMin(&s->gdist[base + 2 * lid],     fenc(da));
        atomicMin(&s->gdist[base + 2 * lid + 1], fenc(dbq));

        // window from upper bounds (real distances -> exact)
        const float d0 = sqrtf(fmaxf(da, 0.0f));
        const float d1 = sqrtf(fmaxf(dbq, 0.0f));
        float wlo = fminf(Q0.y - d0, Q1.y - d1);
        float whi = fmaxf(Q0.y + d0, Q1.y + d1);
#pragma unroll
        for (int o = 16; o > 0; o >>= 1) {
            wlo = fminf(wlo, __shfl_xor_sync(FULL, wlo, o));
            whi = fmaxf(whi, __shfl_xor_sync(FULL, whi, o));
        }
        const int lob = (int)fmaxf(floorf((wlo - ymin) * inv) - 2.0f, 0.0f);
        const int hib = (int)fminf(floorf((whi - ymin) * inv) + 2.0f, (float)(NBIN - 1));
        const int jlo = s->dboff[lob] & ~3;
        const int jhi = min((s->dboff[hib + 1] + 3) & ~3, NPTS);
        const int preh  = min(lo_c, jhi);
        const int postl = max(hi_c, jlo);

        if (lid == 0) {
            int npre  = (preh > jlo)  ? (preh - jlo + CHUNK - 1) / CHUNK : 0;
            int npost = (jhi > postl) ? (jhi - postl + CHUNK - 1) / CHUNK : 0;
            int slot = atomicAdd(&s->nch, npre + npost);
            for (int k = 0; k < npre; k++) {
                s->cg[slot] = g;
                s->clo[slot] = jlo + k * CHUNK;
                s->chi[slot] = min(jlo + (k + 1) * CHUNK, preh);
                slot++;
            }
            for (int k = 0; k < npost; k++) {
                s->cg[slot] = g;
                s->clo[slot] = postl + k * CHUNK;
                s->chi[slot] = min(postl + (k + 1) * CHUNK, jhi);
                slot++;
            }
        }
    }
    __syncthreads();

    // ---- Stage B: dynamic chunk processing ----
    const int nch = s->nch;
    while (true) {
        int i = 0;
        if (lid == 0) i = atomicAdd(&s->cctr, 1);
        i = __shfl_sync(FULL, i, 0);
        if (i >= nch) break;

        const int g   = s->cg[i];
        const int jl  = s->clo[i];
        const int jh  = s->chi[i];
        const int base = g * GSIZE;
        const float4 Q0 = s->qpts[base + 2 * lid];
        const float4 Q1 = s->qpts[base + 2 * lid + 1];
        const ull n00 = pack2(-2.0f * Q0.x, -2.0f * Q0.x);
        const ull n10 = pack2(-2.0f * Q0.y, -2.0f * Q0.y);
        const ull n20 = pack2(-2.0f * Q0.z, -2.0f * Q0.z);
        const ull n01 = pack2(-2.0f * Q1.x, -2.0f * Q1.x);
        const ull n11 = pack2(-2.0f * Q1.y, -2.0f * Q1.y);
        const ull n21 = pack2(-2.0f * Q1.z, -2.0f * Q1.z);
        float m00 = FLT_MAX, m10 = FLT_MAX, m01 = FLT_MAX, m11 = FLT_MAX;

        SCAN_RANGE(jl, jh)

        atomicMin(&s->gdist[base + 2 * lid],     fenc(fminf(m00, m10) + Q0.w));
        atomicMin(&s->gdist[base + 2 * lid + 1], fenc(fminf(m01, m11) + Q1.w));
    }
    __syncthreads();

    // ---- Stage C: fixed-order sum of per-query distances ----
    {
        float ssum = 0.0f;
        for (int i = tid; i < QPB; i += THREADS) ssum += fdec(s->gdist[i]);
#pragma unroll
        for (int o = 16; o > 0; o >>= 1) ssum += __shfl_down_sync(FULL, ssum, o);
        if (lid == 0) s->wred[wid] = ssum;
    }
    __syncthreads();
    if (tid == 0) {
        float t = 0.0f;
#pragma unroll
        for (int w = 0; w < NWARP; w++) t += s->wred[w];
        const int lin = blockIdx.x + SPLITS * (blockIdx.y + 2 * blockIdx.z);
        g_partial[lin] = t;
        __threadfence();
        unsigned int old = atomicAdd(&g_ticket, 1u);
        s->amlast = (old == NBLOCKS - 1);
    }
    __syncthreads();

    // ---- Last block: reduce all 128 partials in fixed order ----
    if (s->amlast) {
        float v = (tid < NBLOCKS) ? g_partial[tid] : 0.0f;
#pragma unroll
        for (int o = 16; o > 0; o >>= 1) v += __shfl_down_sync(FULL, v, o);
        if (lid == 0) s->wred[wid] = v;
        __syncthreads();
        if (tid == 0) {
            float t = 0.0f;
#pragma unroll
            for (int w = 0; w < NWARP; w++) t += s->wred[w];
            out[0] = t * (1.0f / ((float)NB * (float)NPTS));
            g_ticket = 0;   // reset for next graph replay
        }
    }
}

extern "C" void kernel_launch(void* const* d_in, const int* in_sizes, int n_in,
                              void* d_out, int out_size)
{
    const float* x = (const float*)d_in[0];
    const float* y = (const float*)d_in[1];
    float* out = (float*)d_out;

    const int smem = (int)sizeof(SmemLayout);   // ~110 KB
    cudaFuncSetAttribute(chamfer_kernel,
                         cudaFuncAttributeMaxDynamicSharedMemorySize, smem);

    dim3 grid(SPLITS, 2, NB);
    chamfer_kernel<<<grid, THREADS, smem>>>(x, y, out);
}